// round 13
// baseline (speedup 1.0000x reference)
#include <cuda_runtime.h>
#include <mma.h>
#include <cstdint>

using namespace nvcuda;

// Problem constants
#define Bn    512
#define Hh    50
#define Tt    1024
#define STATE 13
#define CTRL  4
#define LAT   128
#define HID   256
#define Dd    8            // decimation factor
#define Jn    (Tt / Dd)    // 128 sequential steps

// ---------------- scratch (no allocations allowed) ----------------
__device__ float  g_h[Bn * HID];
__device__ float  g_E [(size_t)Bn * LAT * LAT];    // raw h@W_A product (bias NOT added)
__device__ float  g_A8[(size_t)Bn * LAT * LAT];    // A^8 (incl. identity)
__device__ float  g_Bm[Bn * LAT * CTRL];
__device__ float  g_M [(size_t)Bn * Dd * LAT * STATE]; // M_r = (A^T)^r Wdec
__device__ float  g_K [Bn * Dd * STATE * CTRL];    // K_k = Wdec^T A^k B
__device__ float  g_d [(size_t)Bn * Jn * LAT];     // d_j
__device__ float  g_z8[(size_t)Bn * (Jn + 1) * LAT];
__device__ float4 g_X4[(size_t)Bn * (Jn + 1) * 32];  // X rows 128-wide: [b][j][r*16+o]

// ---------------- helpers ----------------
__device__ __forceinline__ unsigned long long pack2(float x, float y) {
    unsigned long long r;
    asm("mov.b64 %0, {%1, %2};" : "=l"(r) : "f"(x), "f"(y));
    return r;
}
__device__ __forceinline__ void unpack2(unsigned long long v, float& x, float& y) {
    asm("mov.b64 {%0, %1}, %2;" : "=f"(x), "=f"(y) : "l"(v));
}
__device__ __forceinline__ void ffma2(unsigned long long& d, unsigned long long a,
                                      unsigned long long b) {
    asm("fma.rn.f32x2 %0, %1, %2, %3;" : "=l"(d) : "l"(a), "l"(b), "l"(d));
}
__device__ __forceinline__ float dot4(float4 a, float4 b) {
    return a.x * b.x + a.y * b.y + a.z * b.z + a.w * b.w;
}
#define BAR_POW()   asm volatile("bar.sync 1, 256;" ::: "memory")
#define BAR_MND()   asm volatile("bar.sync 2, 256;" ::: "memory")   // joint MND
#define BAR_NG()    asm volatile("bar.sync 3, 128;" ::: "memory")   // N group
#define BAR_MG()    asm volatile("bar.sync 4, 128;" ::: "memory")   // M group

// ---------------- wmma types ----------------
typedef wmma::fragment<wmma::matrix_a, 16, 16, 8, wmma::precision::tf32, wmma::row_major> FragA;
typedef wmma::fragment<wmma::matrix_a, 16, 16, 8, wmma::precision::tf32, wmma::col_major> FragAc;
typedef wmma::fragment<wmma::matrix_b, 16, 16, 8, wmma::precision::tf32, wmma::row_major> FragBr;
typedef wmma::fragment<wmma::accumulator, 16, 16, 8, float> FragC;

template <typename F>
__device__ __forceinline__ void cvt_tf32(F& f) {
#pragma unroll
    for (int e = 0; e < f.num_elements; e++) f.x[e] = wmma::__float_to_tf32(f.x[e]);
}

// ---------------- kernel 1: context mean + tanh MLP ----------------
__global__ void k_ctxt(const float* __restrict__ xh, const float* __restrict__ uh,
                       const float* __restrict__ Wc, const float* __restrict__ bc) {
    int b = blockIdx.x;
    int tid = threadIdx.x;
    __shared__ float m[STATE + CTRL];

    if (tid < STATE + CTRL) {
        float s = 0.f;
        if (tid < STATE) {
            const float* p = xh + (size_t)b * Hh * STATE + tid;
            for (int r = 0; r < Hh; r++) s += p[r * STATE];
        } else {
            const float* p = uh + (size_t)b * Hh * CTRL + (tid - STATE);
            for (int r = 0; r < Hh; r++) s += p[r * CTRL];
        }
        m[tid] = s * (1.0f / (float)Hh);
    }
    __syncthreads();

    float acc = bc[tid];
#pragma unroll
    for (int c = 0; c < STATE + CTRL; c++) acc += m[c] * Wc[c * HID + tid];
    g_h[b * HID + tid] = tanhf(acc);
}

// ---------------- kernel 2: E = h @ W_A (single-pass tf32) ----------------
__global__ void __launch_bounds__(256)
k_gemmE_tc(const float* __restrict__ WA) {
    __shared__ float sA[128 * 36];
    __shared__ float sB[32 * 132];
    int tid = threadIdx.x, w = tid >> 5;
    int wm = w & 3, wn = w >> 2;
    int n0g = blockIdx.x * 128;
    int m0g = blockIdx.y * 128;

    FragC fc[2][4];
#pragma unroll
    for (int mt = 0; mt < 2; mt++)
#pragma unroll
        for (int nt = 0; nt < 4; nt++) wmma::fill_fragment(fc[mt][nt], 0.f);

    for (int k0 = 0; k0 < HID; k0 += 32) {
        __syncthreads();
#pragma unroll
        for (int p = 0; p < 4; p++) {
            int idx = tid + p * 256;
            int row = idx >> 3, kq = (idx & 7) * 4;
            *(float4*)&sA[row * 36 + kq] =
                *(const float4*)&g_h[(m0g + row) * HID + k0 + kq];
        }
#pragma unroll
        for (int p = 0; p < 4; p++) {
            int idx = tid + p * 256;
            int kkb = idx >> 5, c4 = (idx & 31) * 4;
            *(float4*)&sB[kkb * 132 + c4] =
                *(const float4*)&WA[(size_t)(k0 + kkb) * (LAT * LAT) + n0g + c4];
        }
        __syncthreads();
#pragma unroll
        for (int kk8 = 0; kk8 < 4; kk8++) {
            FragA fa[2];
#pragma unroll
            for (int mt = 0; mt < 2; mt++) {
                wmma::load_matrix_sync(fa[mt], &sA[(wm * 32 + mt * 16) * 36 + kk8 * 8], 36);
                cvt_tf32(fa[mt]);
            }
#pragma unroll
            for (int nt = 0; nt < 4; nt++) {
                FragBr fb;
                wmma::load_matrix_sync(fb, &sB[(kk8 * 8) * 132 + wn * 64 + nt * 16], 132);
                cvt_tf32(fb);
                wmma::mma_sync(fc[0][nt], fa[0], fb, fc[0][nt]);
                wmma::mma_sync(fc[1][nt], fa[1], fb, fc[1][nt]);
            }
        }
    }
#pragma unroll
    for (int mt = 0; mt < 2; mt++)
#pragma unroll
        for (int nt = 0; nt < 4; nt++)
            wmma::store_matrix_sync(
                &g_E[(size_t)(m0g + wm * 32 + mt * 16) * (LAT * LAT) +
                     n0g + wn * 64 + nt * 16],
                fc[mt][nt], LAT * LAT, wmma::mem_row_major);
}

// ---------------- kernel 3: B_mat = h @ W_B + b_B ----------------
__global__ void k_gemmB(const float* __restrict__ WB, const float* __restrict__ bB) {
    int b = blockIdx.x;
    int tid = threadIdx.x;
    __shared__ float hs[HID];
    hs[tid] = g_h[b * HID + tid];
    __syncthreads();
    for (int c = tid; c < LAT * CTRL; c += 256) {
        float acc = bB[c];
#pragma unroll 8
        for (int k = 0; k < HID; k++) acc += hs[k] * WB[k * (LAT * CTRL) + c];
        g_Bm[b * (LAT * CTRL) + c] = acc;
    }
}

// ================= fused k_powmnd: warp-specialized, 3-way =================
// 512 threads. Warps 0-7: tf32 squaring rounds (-> g_A8).
// Warps 8-11: N recurrence + K (uses sWd, since M group mutates sMp).
// Warps 12-15: M recurrence on tensor cores. Join for d phase.
#define PLD 132
__global__ void __launch_bounds__(512)
k_powmnd(const float* __restrict__ bA, const float* __restrict__ Wdec,
         const float* __restrict__ u) {
    extern __shared__ float dsm[];
    float* sX    = dsm;                      // 128*132 (tf32-rounded, pow's buffer)
    float* sE    = sX + 128 * PLD;           // 128*132 (fp32, mnd's buffer)
    float* sMp   = sE + 128 * PLD;           // 128*16  (M padded, mutated by M group)
    float* sWd   = sMp + 128 * 16;           // 128*13  (stable Wdec copy for K)
    float* sNall = sWd + 128 * STATE;        // 8*128*4
    float* su    = sNall + 8 * 128 * 4;      // 1024*4
    int b = blockIdx.x, tid = threadIdx.x;
    const float* Eb = g_E + (size_t)b * (LAT * LAT);

    // joint load: E + bias -> sE (fp32) and sX (tf32-rounded)
#pragma unroll
    for (int p = 0; p < 8; p++) {
        int idx = tid + p * 512;
        int row = idx >> 5, c4 = (idx & 31) * 4;
        float4 e = *(const float4*)&Eb[row * 128 + c4];
        float4 bb = *(const float4*)&bA[row * 128 + c4];
        e.x += bb.x; e.y += bb.y; e.z += bb.z; e.w += bb.w;
        *(float4*)&sE[row * PLD + c4] = e;
        e.x = wmma::__float_to_tf32(e.x);
        e.y = wmma::__float_to_tf32(e.y);
        e.z = wmma::__float_to_tf32(e.z);
        e.w = wmma::__float_to_tf32(e.w);
        *(float4*)&sX[row * PLD + c4] = e;
    }
    __syncthreads();

    if (tid < 256) {
        // ================= POW half (warps 0-7) =================
        int w = tid >> 5, wm = w & 3, wn = w >> 2;
        float* A8b = g_A8 + (size_t)b * (LAT * LAT);

        for (int rnd = 0; rnd < 3; rnd++) {
            FragC fc[2][4];
#pragma unroll
            for (int mt = 0; mt < 2; mt++)
#pragma unroll
                for (int nt = 0; nt < 4; nt++) wmma::fill_fragment(fc[mt][nt], 0.f);

#pragma unroll 4
            for (int kk = 0; kk < 16; kk++) {
                FragA fa[2];
#pragma unroll
                for (int mt = 0; mt < 2; mt++)
                    wmma::load_matrix_sync(fa[mt], &sX[(wm * 32 + mt * 16) * PLD + kk * 8], PLD);
#pragma unroll
                for (int nt = 0; nt < 4; nt++) {
                    FragBr fb;
                    wmma::load_matrix_sync(fb, &sX[(kk * 8) * PLD + wn * 64 + nt * 16], PLD);
                    wmma::mma_sync(fc[0][nt], fa[0], fb, fc[0][nt]);
                    wmma::mma_sync(fc[1][nt], fa[1], fb, fc[1][nt]);
                }
            }
            BAR_POW();

            int r0l = tid >> 3;
            int cb = (tid & 7) * 16;
#pragma unroll
            for (int ph = 0; ph < 4; ph++) {
                int row = ph * 32 + r0l;
                float4 st[4];
#pragma unroll
                for (int q = 0; q < 4; q++) st[q] = *(float4*)&sX[row * PLD + cb + q * 4];
                BAR_POW();
                if (wm == ph) {
#pragma unroll
                    for (int mt = 0; mt < 2; mt++)
#pragma unroll
                        for (int nt = 0; nt < 4; nt++)
                            wmma::store_matrix_sync(
                                &sX[(ph * 32 + mt * 16) * PLD + wn * 64 + nt * 16],
                                fc[mt][nt], PLD, wmma::mem_row_major);
                }
                BAR_POW();
                if (rnd < 2) {
#pragma unroll
                    for (int q = 0; q < 4; q++) {
                        float4 y = *(float4*)&sX[row * PLD + cb + q * 4];
                        y.x = wmma::__float_to_tf32(y.x + 2.f * st[q].x);
                        y.y = wmma::__float_to_tf32(y.y + 2.f * st[q].y);
                        y.z = wmma::__float_to_tf32(y.z + 2.f * st[q].z);
                        y.w = wmma::__float_to_tf32(y.w + 2.f * st[q].w);
                        *(float4*)&sX[row * PLD + cb + q * 4] = y;
                    }
                } else {
#pragma unroll
                    for (int q = 0; q < 4; q++) {
                        float4 y = *(float4*)&sX[row * PLD + cb + q * 4];
                        int c0 = cb + q * 4;
                        y.x += 2.f * st[q].x + ((row == c0 + 0) ? 1.f : 0.f);
                        y.y += 2.f * st[q].y + ((row == c0 + 1) ? 1.f : 0.f);
                        y.z += 2.f * st[q].z + ((row == c0 + 2) ? 1.f : 0.f);
                        y.w += 2.f * st[q].w + ((row == c0 + 3) ? 1.f : 0.f);
                        *(float4*)&A8b[row * 128 + c0] = y;
                    }
                }
                BAR_POW();
            }
        }
    } else {
        // ================= MND half (warps 8-15) =================
        int tm = tid - 256;   // 0..255

        // joint init: M_0 = Wdec (padded), Wdec copy, N_0 = Bm, u staged
        for (int t = tm; t < 128 * 16; t += 256) {
            int row = t >> 4, o = t & 15;
            sMp[t] = (o < STATE) ? Wdec[row * STATE + o] : 0.f;
        }
        for (int t = tm; t < LAT * STATE; t += 256) sWd[t] = Wdec[t];
        for (int t = tm; t < LAT * CTRL; t += 256) sNall[t] = g_Bm[b * LAT * CTRL + t];
#pragma unroll
        for (int p = 0; p < 4; p++) {
            int idx = tm + p * 256;
            *(float4*)&su[idx * 4] = *(const float4*)&u[((size_t)b * Tt + idx) * CTRL];
        }
        BAR_MND();

        if (tm < 128) {
            // ---- group A (warps 8-11): N recurrence + K ----
            int i = tm;
            // K_0
            if (tm < STATE * CTRL) {
                int o = tm >> 2, c = tm & 3;
                float acc = 0.f;
                for (int ii = 0; ii < LAT; ii++) acc += sWd[ii * STATE + o] * sNall[ii * CTRL + c];
                g_K[(b * Dd) * STATE * CTRL + tm] = acc;
            }
            for (int k = 1; k < Dd; k++) {
                const float* Np = &sNall[(k - 1) * 512];
                float4 a = *(float4*)&Np[i * 4];
                const float* erow = &sE[i * PLD];
#pragma unroll 8
                for (int l = 0; l < LAT; l++) {
                    float e = erow[l];
                    float4 n = *(float4*)&Np[l * 4];
                    a.x += e * n.x; a.y += e * n.y; a.z += e * n.z; a.w += e * n.w;
                }
                *(float4*)&sNall[k * 512 + i * 4] = a;
                BAR_NG();
                if (tm < STATE * CTRL) {
                    int o = tm >> 2, c = tm & 3;
                    float acc = 0.f;
                    for (int ii = 0; ii < LAT; ii++)
                        acc += sWd[ii * STATE + o] * sNall[k * 512 + ii * CTRL + c];
                    g_K[(b * Dd + k) * STATE * CTRL + tm] = acc;
                }
            }
        } else {
            // ---- group B (warps 12-15): M recurrence on tensor ----
            int tg = tm - 128;      // 0..127
            int wq = tg >> 5;       // 0..3, rows wq*32..+31

            // write M_0
            for (int t = tg; t < LAT * STATE; t += 128)
                g_M[(size_t)(b * Dd) * LAT * STATE + t] = sWd[t];

            for (int r = 1; r < Dd; r++) {
                FragC fm[2];
                wmma::fill_fragment(fm[0], 0.f);
                wmma::fill_fragment(fm[1], 0.f);
#pragma unroll 4
                for (int kk = 0; kk < 16; kk++) {
                    FragBr fb;
                    wmma::load_matrix_sync(fb, &sMp[(kk * 8) * 16], 16);
                    cvt_tf32(fb);
#pragma unroll
                    for (int mt = 0; mt < 2; mt++) {
                        FragAc fa;
                        wmma::load_matrix_sync(fa, &sE[(kk * 8) * PLD + wq * 32 + mt * 16], PLD);
                        cvt_tf32(fa);
                        wmma::mma_sync(fm[mt], fa, fb, fm[mt]);
                    }
                }
                // in-place epilogue (128 threads: row = tg, 16 cols each)
                float4 st0, st1, st2, st3;
                st0 = *(float4*)&sMp[tg * 16];
                st1 = *(float4*)&sMp[tg * 16 + 4];
                st2 = *(float4*)&sMp[tg * 16 + 8];
                st3 = *(float4*)&sMp[tg * 16 + 12];
                BAR_MG();
                wmma::store_matrix_sync(&sMp[(wq * 32) * 16], fm[0], 16, wmma::mem_row_major);
                wmma::store_matrix_sync(&sMp[(wq * 32 + 16) * 16], fm[1], 16, wmma::mem_row_major);
                BAR_MG();
                {
                    float4 y0 = *(float4*)&sMp[tg * 16];
                    float4 y1 = *(float4*)&sMp[tg * 16 + 4];
                    float4 y2 = *(float4*)&sMp[tg * 16 + 8];
                    float4 y3 = *(float4*)&sMp[tg * 16 + 12];
                    y0.x += st0.x; y0.y += st0.y; y0.z += st0.z; y0.w += st0.w;
                    y1.x += st1.x; y1.y += st1.y; y1.z += st1.z; y1.w += st1.w;
                    y2.x += st2.x; y2.y += st2.y; y2.z += st2.z; y2.w += st2.w;
                    y3.x += st3.x; y3.y += st3.y; y3.z += st3.z; y3.w += st3.w;
                    *(float4*)&sMp[tg * 16]      = y0;
                    *(float4*)&sMp[tg * 16 + 4]  = y1;
                    *(float4*)&sMp[tg * 16 + 8]  = y2;
                    *(float4*)&sMp[tg * 16 + 12] = y3;
                }
                BAR_MG();
                for (int t = tg; t < LAT * STATE; t += 128)
                    g_M[(size_t)(b * Dd + r) * LAT * STATE + t] =
                        sMp[(t / STATE) * 16 + (t % STATE)];
            }
        }
        BAR_MND();   // join groups: N done (for d), M done

        // d_j = sum_r N_{7-r} u_{8j+r}  (all 256 MND threads)
        {
            int i = tm & 127, jh = tm >> 7;
            for (int jj = 0; jj < 64; jj++) {
                int j = jj * 2 + jh;
                float acc = 0.f;
#pragma unroll
                for (int r = 0; r < Dd; r++) {
                    float4 n = *(float4*)&sNall[(7 - r) * 512 + i * 4];
                    float4 uu = *(float4*)&su[(8 * j + r) * 4];
                    acc += dot4(n, uu);
                }
                g_d[((size_t)b * Jn + j) * LAT + i] = acc;
            }
        }
    }
}

// ---------------- decimated scan: 128 steps with A^8, 4-deep d prefetch ----------------
__global__ void __launch_bounds__(128, 4)
k_scan(const float* __restrict__ x_init, const float* __restrict__ Wenc,
       const float* __restrict__ benc) {
    int b = blockIdx.x;
    int i = threadIdx.x;

    __shared__ float zs[2][LAT];
    __shared__ float xi[16];

    ulonglong2 a[32];
    const ulonglong2* Ab = (const ulonglong2*)(g_A8 + (size_t)b * (LAT * LAT) + (size_t)i * LAT);
#pragma unroll
    for (int t = 0; t < 32; t++) a[t] = Ab[t];

    if (i < STATE) xi[i] = x_init[b * STATE + i];
    __syncthreads();

    float z0 = benc[i];
#pragma unroll
    for (int s = 0; s < STATE; s++) z0 += xi[s] * Wenc[s * LAT + i];
    zs[0][i] = z0;
    g_z8[(size_t)b * (Jn + 1) * LAT + i] = z0;
    __syncthreads();

    const float* db = g_d + (size_t)b * Jn * LAT;
    float dreg[4];
#pragma unroll
    for (int p = 0; p < 4; p++) dreg[p] = db[p * LAT + i];
    int cur = 0;

#pragma unroll 4
    for (int k = 0; k < Jn; k++) {
        float ci = dreg[k & 3];
        if (k + 4 < Jn) dreg[k & 3] = db[(k + 4) * LAT + i];

        const ulonglong2* zv2 = (const ulonglong2*)zs[cur];
        unsigned long long acc0 = pack2(ci, 0.f);
        unsigned long long acc1 = 0ULL, acc2 = 0ULL, acc3 = 0ULL;
#pragma unroll
        for (int t = 0; t < 32; t += 2) {
            ulonglong2 zva = zv2[t];
            ulonglong2 zvb = zv2[t + 1];
            ffma2(acc0, a[t].x, zva.x);
            ffma2(acc1, a[t].y, zva.y);
            ffma2(acc2, a[t + 1].x, zvb.x);
            ffma2(acc3, a[t + 1].y, zvb.y);
        }
        float s0, s1, s2, s3, s4, s5, s6, s7;
        unpack2(acc0, s0, s1); unpack2(acc1, s2, s3);
        unpack2(acc2, s4, s5); unpack2(acc3, s6, s7);
        float zn = ((s0 + s2) + (s1 + s3)) + ((s4 + s6) + (s5 + s7));

        zs[cur ^ 1][i] = zn;
        g_z8[((size_t)b * (Jn + 1) + k + 1) * LAT + i] = zn;
        __syncthreads();
        cur ^= 1;
    }
}

// ---------------- X GEMM: X[j][r*16+o] = z8[j] . M_r[:,o] ----------------
#define XP 132
__global__ void __launch_bounds__(256)
k_xg() {
    __align__(16) __shared__ float sZ[32 * XP];   // [kk][j], j=0..128
    __align__(16) __shared__ float sM2[32 * XP];  // [kk][r*16+o]
    int b = blockIdx.x, tid = threadIdx.x;
    int ry = tid >> 3;
    int cx = tid & 7;

    __align__(16) unsigned long long acc2[4][8];
#pragma unroll
    for (int q = 0; q < 4; q++)
#pragma unroll
        for (int p = 0; p < 8; p++) acc2[q][p] = 0ULL;
    float acc128 = 0.f;
    int r13 = 0, o13 = 0;
    if (tid < 104) { r13 = tid / 13; o13 = tid % 13; }

    for (int k0 = 0; k0 < 128; k0 += 32) {
        __syncthreads();
        for (int t = tid; t < 129 * 32; t += 256) {
            int j = t >> 5, kk = t & 31;
            sZ[kk * XP + j] = g_z8[((size_t)b * (Jn + 1) + j) * LAT + k0 + kk];
        }
        for (int t = tid; t < 32 * 128; t += 256) {
            int kk = t >> 7, col = t & 127;
            int r = col >> 4, o = col & 15;
            sM2[kk * XP + col] =
                (o < STATE) ? g_M[((size_t)(b * Dd + r) * LAT + k0 + kk) * STATE + o] : 0.f;
        }
        __syncthreads();
#pragma unroll
        for (int kk = 0; kk < 32; kk++) {
            float4 a4 = *(float4*)&sZ[kk * XP + ry * 4];
            ulonglong2 bb0 = *(ulonglong2*)&sM2[kk * XP + cx * 16];
            ulonglong2 bb1 = *(ulonglong2*)&sM2[kk * XP + cx * 16 + 4];
            ulonglong2 bb2 = *(ulonglong2*)&sM2[kk * XP + cx * 16 + 8];
            ulonglong2 bb3 = *(ulonglong2*)&sM2[kk * XP + cx * 16 + 12];
            unsigned long long bb[8] = {bb0.x, bb0.y, bb1.x, bb1.y, bb2.x, bb2.y, bb3.x, bb3.y};
            float av[4] = {a4.x, a4.y, a4.z, a4.w};
#pragma unroll
            for (int q = 0; q < 4; q++) {
                unsigned long long a2 = pack2(av[q], av[q]);
#pragma unroll
                for (int p = 0; p < 8; p++) ffma2(acc2[q][p], a2, bb[p]);
            }
        }
        if (tid < 104) {
            float accl = 0.f;
            for (int kk = 0; kk < 32; kk++)
                accl += sZ[kk * XP + 128] * sM2[kk * XP + r13 * 16 + o13];
            acc128 += accl;
        }
    }
    float* X = (float*)g_X4;
#pragma unroll
    for (int q = 0; q < 4; q++) {
        int j = ry * 4 + q;
        size_t base = ((size_t)b * (Jn + 1) + j) * 128 + cx * 16;
        *(float4*)&X[base]      = *(float4*)&acc2[q][0];
        *(float4*)&X[base + 4]  = *(float4*)&acc2[q][2];
        *(float4*)&X[base + 8]  = *(float4*)&acc2[q][4];
        *(float4*)&X[base + 12] = *(float4*)&acc2[q][6];
    }
    if (tid < 104)
        X[((size_t)b * (Jn + 1) + 128) * 128 + r13 * 16 + o13] = acc128;
}

// ---------------- final: u-corrections + bias + normalize + write out ----------------
__global__ void __launch_bounds__(256)
k_norm(const float* __restrict__ u, const float* __restrict__ bdec,
       float* __restrict__ outp) {
    int b = blockIdx.y, t0 = blockIdx.x * 256, tid = threadIdx.x;
    __shared__ float sK[Dd * STATE * CTRL];
    __shared__ float4 su[256];
    __shared__ float sb[STATE];
    __shared__ float sO[256 * STATE];

    for (int q = tid; q < Dd * STATE * CTRL; q += 256) sK[q] = g_K[b * Dd * STATE * CTRL + q];
    if (t0 + tid < Tt) su[tid] = *(const float4*)&u[((size_t)b * Tt + t0 + tid) * CTRL];
    if (tid < STATE) sb[tid] = bdec[tid];
    __syncthreads();

    int t = t0 + tid;
    if (t <= Tt) {
        int j = t >> 3, r = t & 7;
        const float* xr = (const float*)g_X4 + ((size_t)b * (Jn + 1) + j) * 128 + r * 16;
        float4 x0 = *(const float4*)&xr[0];
        float4 x1 = *(const float4*)&xr[4];
        float4 x2 = *(const float4*)&xr[8];
        float4 x3 = *(const float4*)&xr[12];
        float x[13] = {x0.x, x0.y, x0.z, x0.w, x1.x, x1.y, x1.z, x1.w,
                       x2.x, x2.y, x2.z, x2.w, x3.x};
#pragma unroll
        for (int o = 0; o < STATE; o++) x[o] += sb[o];
        for (int s = 0; s < r; s++) {
            float4 uu = su[tid - r + s];
            const float* Kp = &sK[(r - 1 - s) * STATE * CTRL];
#pragma unroll
            for (int o = 0; o < STATE; o++)
                x[o] += Kp[o * 4 + 0] * uu.x + Kp[o * 4 + 1] * uu.y +
                        Kp[o * 4 + 2] * uu.z + Kp[o * 4 + 3] * uu.w;
        }
        float nrm = sqrtf(x[3] * x[3] + x[4] * x[4] + x[5] * x[5] + x[6] * x[6]);
        float inv = 1.0f / fmaxf(nrm, 1e-12f);
        x[3] *= inv; x[4] *= inv; x[5] *= inv; x[6] *= inv;
#pragma unroll
        for (int o = 0; o < STATE; o++) sO[tid * STATE + o] = x[o];
    }
    __syncthreads();
    int nrow = Tt + 1 - t0;
    if (nrow > 256) nrow = 256;
    if (nrow < 0) nrow = 0;
    for (int q = tid; q < nrow * STATE; q += 256)
        outp[((size_t)b * (Tt + 1) + t0) * STATE + q] = sO[q];
}

// ---------------- launcher ----------------
extern "C" void kernel_launch(void* const* d_in, const int* in_sizes, int n_in,
                              void* d_out, int out_size) {
    const float* x_history = (const float*)d_in[0];
    const float* u_history = (const float*)d_in[1];
    const float* x_init    = (const float*)d_in[2];
    const float* u_future  = (const float*)d_in[4];
    const float* W_ctxt    = (const float*)d_in[6];
    const float* b_ctxt    = (const float*)d_in[7];
    const float* W_A       = (const float*)d_in[8];
    const float* b_A       = (const float*)d_in[9];
    const float* W_B       = (const float*)d_in[10];
    const float* b_B       = (const float*)d_in[11];
    const float* W_enc     = (const float*)d_in[12];
    const float* b_enc     = (const float*)d_in[13];
    const float* W_dec     = (const float*)d_in[14];
    const float* b_dec     = (const float*)d_in[15];
    float* out = (float*)d_out;

    // sX + sE + sMp + sWd + sNall + su
    const int PM_SMEM =
        (128 * PLD + 128 * PLD + 128 * 16 + 128 * STATE + 8 * 128 * 4 + 1024 * 4) * 4;
    cudaFuncSetAttribute(k_powmnd, cudaFuncAttributeMaxDynamicSharedMemorySize, PM_SMEM);

    k_ctxt<<<Bn, 256>>>(x_history, u_history, W_ctxt, b_ctxt);
    k_gemmE_tc<<<dim3(128, 4), 256>>>(W_A);
    k_gemmB<<<Bn, 256>>>(W_B, b_B);

    k_powmnd<<<Bn, 512, PM_SMEM>>>(b_A, W_dec, u_future);

    k_scan<<<Bn, 128>>>(x_init, W_enc, b_enc);

    k_xg<<<Bn, 256>>>();
    k_norm<<<dim3(5, Bn), 256>>>(u_future, b_dec, out);
}

// round 14
// speedup vs baseline: 1.1421x; 1.1421x over previous
#include <cuda_runtime.h>
#include <mma.h>
#include <cstdint>

using namespace nvcuda;

// Problem constants
#define Bn    512
#define Hh    50
#define Tt    1024
#define STATE 13
#define CTRL  4
#define LAT   128
#define HID   256
#define Dd    8            // decimation factor
#define Jn    (Tt / Dd)    // 128 sequential steps

// ---------------- scratch (no allocations allowed) ----------------
__device__ float  g_h[Bn * HID];
__device__ float  g_E [(size_t)Bn * LAT * LAT];    // raw h@W_A product (bias NOT added)
__device__ float  g_A8[(size_t)Bn * LAT * LAT];    // A^8 (incl. identity)
__device__ float  g_Bm[Bn * LAT * CTRL];
__device__ float  g_M [(size_t)Bn * Dd * LAT * STATE]; // M_r = (A^T)^r Wdec
__device__ float  g_K [Bn * Dd * STATE * CTRL];    // K_k = Wdec^T A^k B
__device__ float  g_d [(size_t)Bn * Jn * LAT];     // d_j
__device__ float  g_z8[(size_t)Bn * (Jn + 1) * LAT];
__device__ float4 g_X4[(size_t)Bn * (Jn + 1) * 32];  // X rows 128-wide: [b][j][r*16+o]

// ---------------- helpers ----------------
__device__ __forceinline__ unsigned long long pack2(float x, float y) {
    unsigned long long r;
    asm("mov.b64 %0, {%1, %2};" : "=l"(r) : "f"(x), "f"(y));
    return r;
}
__device__ __forceinline__ void unpack2(unsigned long long v, float& x, float& y) {
    asm("mov.b64 {%0, %1}, %2;" : "=f"(x), "=f"(y) : "l"(v));
}
__device__ __forceinline__ void ffma2(unsigned long long& d, unsigned long long a,
                                      unsigned long long b) {
    asm("fma.rn.f32x2 %0, %1, %2, %3;" : "=l"(d) : "l"(a), "l"(b), "l"(d));
}
__device__ __forceinline__ float dot4(float4 a, float4 b) {
    return a.x * b.x + a.y * b.y + a.z * b.z + a.w * b.w;
}
__device__ __forceinline__ void cp_async16(void* smem_dst, const void* gmem_src) {
    uint32_t s = (uint32_t)__cvta_generic_to_shared(smem_dst);
    asm volatile("cp.async.cg.shared.global [%0], [%1], 16;" :: "r"(s), "l"(gmem_src));
}
#define CP_COMMIT()  asm volatile("cp.async.commit_group;" ::: "memory")
#define CP_WAIT1()   asm volatile("cp.async.wait_group 1;" ::: "memory")
#define CP_WAIT0()   asm volatile("cp.async.wait_group 0;" ::: "memory")
#define BAR_POW()   asm volatile("bar.sync 1, 256;" ::: "memory")
#define BAR_MND()   asm volatile("bar.sync 2, 256;" ::: "memory")
#define BAR_NG()    asm volatile("bar.sync 3, 128;" ::: "memory")
#define BAR_MG()    asm volatile("bar.sync 4, 128;" ::: "memory")

// ---------------- wmma types ----------------
typedef wmma::fragment<wmma::matrix_a, 16, 16, 8, wmma::precision::tf32, wmma::row_major> FragA;
typedef wmma::fragment<wmma::matrix_a, 16, 16, 8, wmma::precision::tf32, wmma::col_major> FragAc;
typedef wmma::fragment<wmma::matrix_b, 16, 16, 8, wmma::precision::tf32, wmma::row_major> FragBr;
typedef wmma::fragment<wmma::accumulator, 16, 16, 8, float> FragC;

template <typename F>
__device__ __forceinline__ void cvt_tf32(F& f) {
#pragma unroll
    for (int e = 0; e < f.num_elements; e++) f.x[e] = wmma::__float_to_tf32(f.x[e]);
}

// ---------------- kernel 1: context mean + tanh MLP ----------------
__global__ void k_ctxt(const float* __restrict__ xh, const float* __restrict__ uh,
                       const float* __restrict__ Wc, const float* __restrict__ bc) {
    int b = blockIdx.x;
    int tid = threadIdx.x;
    __shared__ float m[STATE + CTRL];

    if (tid < STATE + CTRL) {
        float s = 0.f;
        if (tid < STATE) {
            const float* p = xh + (size_t)b * Hh * STATE + tid;
            for (int r = 0; r < Hh; r++) s += p[r * STATE];
        } else {
            const float* p = uh + (size_t)b * Hh * CTRL + (tid - STATE);
            for (int r = 0; r < Hh; r++) s += p[r * CTRL];
        }
        m[tid] = s * (1.0f / (float)Hh);
    }
    __syncthreads();

    float acc = bc[tid];
#pragma unroll
    for (int c = 0; c < STATE + CTRL; c++) acc += m[c] * Wc[c * HID + tid];
    g_h[b * HID + tid] = tanhf(acc);
}

// ---------------- kernel 2: E = h @ W_A (tf32, cp.async double-buffered) ----------------
__global__ void __launch_bounds__(256)
k_gemmE_tc(const float* __restrict__ WA) {
    extern __shared__ float esm[];
    float* sA = esm;                  // [2][128*36]
    float* sB = esm + 2 * 128 * 36;   // [2][32*132]
    int tid = threadIdx.x, w = tid >> 5;
    int wm = w & 3, wn = w >> 2;
    int n0g = blockIdx.x * 128;
    int m0g = blockIdx.y * 128;

    FragC fc[2][4];
#pragma unroll
    for (int mt = 0; mt < 2; mt++)
#pragma unroll
        for (int nt = 0; nt < 4; nt++) wmma::fill_fragment(fc[mt][nt], 0.f);

    auto stage = [&](int buf, int k0) {
        float* dA = sA + buf * (128 * 36);
        float* dB = sB + buf * (32 * 132);
#pragma unroll
        for (int p = 0; p < 4; p++) {
            int idx = tid + p * 256;
            int row = idx >> 3, kq = (idx & 7) * 4;
            cp_async16(&dA[row * 36 + kq], &g_h[(m0g + row) * HID + k0 + kq]);
        }
#pragma unroll
        for (int p = 0; p < 4; p++) {
            int idx = tid + p * 256;
            int kkb = idx >> 5, c4 = (idx & 31) * 4;
            cp_async16(&dB[kkb * 132 + c4],
                       &WA[(size_t)(k0 + kkb) * (LAT * LAT) + n0g + c4]);
        }
        CP_COMMIT();
    };

    stage(0, 0);
    for (int c = 0; c < 8; c++) {
        if (c + 1 < 8) {
            stage((c + 1) & 1, (c + 1) * 32);
            CP_WAIT1();
        } else {
            CP_WAIT0();
        }
        __syncthreads();
        const float* cA = sA + (c & 1) * (128 * 36);
        const float* cB = sB + (c & 1) * (32 * 132);
#pragma unroll
        for (int kk8 = 0; kk8 < 4; kk8++) {
            FragA fa[2];
#pragma unroll
            for (int mt = 0; mt < 2; mt++) {
                wmma::load_matrix_sync(fa[mt], &cA[(wm * 32 + mt * 16) * 36 + kk8 * 8], 36);
                cvt_tf32(fa[mt]);
            }
#pragma unroll
            for (int nt = 0; nt < 4; nt++) {
                FragBr fb;
                wmma::load_matrix_sync(fb, &cB[(kk8 * 8) * 132 + wn * 64 + nt * 16], 132);
                cvt_tf32(fb);
                wmma::mma_sync(fc[0][nt], fa[0], fb, fc[0][nt]);
                wmma::mma_sync(fc[1][nt], fa[1], fb, fc[1][nt]);
            }
        }
        __syncthreads();
    }
#pragma unroll
    for (int mt = 0; mt < 2; mt++)
#pragma unroll
        for (int nt = 0; nt < 4; nt++)
            wmma::store_matrix_sync(
                &g_E[(size_t)(m0g + wm * 32 + mt * 16) * (LAT * LAT) +
                     n0g + wn * 64 + nt * 16],
                fc[mt][nt], LAT * LAT, wmma::mem_row_major);
}

// ---------------- kernel 3: B_mat = h @ W_B + b_B ----------------
__global__ void k_gemmB(const float* __restrict__ WB, const float* __restrict__ bB) {
    int b = blockIdx.x;
    int tid = threadIdx.x;
    __shared__ float hs[HID];
    hs[tid] = g_h[b * HID + tid];
    __syncthreads();
    for (int c = tid; c < LAT * CTRL; c += 256) {
        float acc = bB[c];
#pragma unroll 8
        for (int k = 0; k < HID; k++) acc += hs[k] * WB[k * (LAT * CTRL) + c];
        g_Bm[b * (LAT * CTRL) + c] = acc;
    }
}

// ================= fused k_powmnd: warp-specialized, 3-way =================
#define PLD 132
__global__ void __launch_bounds__(512)
k_powmnd(const float* __restrict__ bA, const float* __restrict__ Wdec,
         const float* __restrict__ u) {
    extern __shared__ float dsm[];
    float* sX    = dsm;                      // 128*132 (tf32-rounded, pow's buffer)
    float* sE    = sX + 128 * PLD;           // 128*132 (fp32, mnd's buffer)
    float* sMp   = sE + 128 * PLD;           // 128*16
    float* sWd   = sMp + 128 * 16;           // 128*13
    float* sNall = sWd + 128 * STATE;        // 8*128*4
    float* su    = sNall + 8 * 128 * 4;      // 1024*4
    int b = blockIdx.x, tid = threadIdx.x;
    const float* Eb = g_E + (size_t)b * (LAT * LAT);

#pragma unroll
    for (int p = 0; p < 8; p++) {
        int idx = tid + p * 512;
        int row = idx >> 5, c4 = (idx & 31) * 4;
        float4 e = *(const float4*)&Eb[row * 128 + c4];
        float4 bb = *(const float4*)&bA[row * 128 + c4];
        e.x += bb.x; e.y += bb.y; e.z += bb.z; e.w += bb.w;
        *(float4*)&sE[row * PLD + c4] = e;
        e.x = wmma::__float_to_tf32(e.x);
        e.y = wmma::__float_to_tf32(e.y);
        e.z = wmma::__float_to_tf32(e.z);
        e.w = wmma::__float_to_tf32(e.w);
        *(float4*)&sX[row * PLD + c4] = e;
    }
    __syncthreads();

    if (tid < 256) {
        // ================= POW half (warps 0-7) =================
        int w = tid >> 5, wm = w & 3, wn = w >> 2;
        float* A8b = g_A8 + (size_t)b * (LAT * LAT);

        for (int rnd = 0; rnd < 3; rnd++) {
            FragC fc[2][4];
#pragma unroll
            for (int mt = 0; mt < 2; mt++)
#pragma unroll
                for (int nt = 0; nt < 4; nt++) wmma::fill_fragment(fc[mt][nt], 0.f);

#pragma unroll 4
            for (int kk = 0; kk < 16; kk++) {
                FragA fa[2];
#pragma unroll
                for (int mt = 0; mt < 2; mt++)
                    wmma::load_matrix_sync(fa[mt], &sX[(wm * 32 + mt * 16) * PLD + kk * 8], PLD);
#pragma unroll
                for (int nt = 0; nt < 4; nt++) {
                    FragBr fb;
                    wmma::load_matrix_sync(fb, &sX[(kk * 8) * PLD + wn * 64 + nt * 16], PLD);
                    wmma::mma_sync(fc[0][nt], fa[0], fb, fc[0][nt]);
                    wmma::mma_sync(fc[1][nt], fa[1], fb, fc[1][nt]);
                }
            }
            BAR_POW();

            int r0l = tid >> 3;
            int cb = (tid & 7) * 16;
#pragma unroll
            for (int ph = 0; ph < 4; ph++) {
                int row = ph * 32 + r0l;
                float4 st[4];
#pragma unroll
                for (int q = 0; q < 4; q++) st[q] = *(float4*)&sX[row * PLD + cb + q * 4];
                BAR_POW();
                if (wm == ph) {
#pragma unroll
                    for (int mt = 0; mt < 2; mt++)
#pragma unroll
                        for (int nt = 0; nt < 4; nt++)
                            wmma::store_matrix_sync(
                                &sX[(ph * 32 + mt * 16) * PLD + wn * 64 + nt * 16],
                                fc[mt][nt], PLD, wmma::mem_row_major);
                }
                BAR_POW();
                if (rnd < 2) {
#pragma unroll
                    for (int q = 0; q < 4; q++) {
                        float4 y = *(float4*)&sX[row * PLD + cb + q * 4];
                        y.x = wmma::__float_to_tf32(y.x + 2.f * st[q].x);
                        y.y = wmma::__float_to_tf32(y.y + 2.f * st[q].y);
                        y.z = wmma::__float_to_tf32(y.z + 2.f * st[q].z);
                        y.w = wmma::__float_to_tf32(y.w + 2.f * st[q].w);
                        *(float4*)&sX[row * PLD + cb + q * 4] = y;
                    }
                } else {
#pragma unroll
                    for (int q = 0; q < 4; q++) {
                        float4 y = *(float4*)&sX[row * PLD + cb + q * 4];
                        int c0 = cb + q * 4;
                        y.x += 2.f * st[q].x + ((row == c0 + 0) ? 1.f : 0.f);
                        y.y += 2.f * st[q].y + ((row == c0 + 1) ? 1.f : 0.f);
                        y.z += 2.f * st[q].z + ((row == c0 + 2) ? 1.f : 0.f);
                        y.w += 2.f * st[q].w + ((row == c0 + 3) ? 1.f : 0.f);
                        *(float4*)&A8b[row * 128 + c0] = y;
                    }
                }
                BAR_POW();
            }
        }
    } else {
        // ================= MND half (warps 8-15) =================
        int tm = tid - 256;

        for (int t = tm; t < 128 * 16; t += 256) {
            int row = t >> 4, o = t & 15;
            sMp[t] = (o < STATE) ? Wdec[row * STATE + o] : 0.f;
        }
        for (int t = tm; t < LAT * STATE; t += 256) sWd[t] = Wdec[t];
        for (int t = tm; t < LAT * CTRL; t += 256) sNall[t] = g_Bm[b * LAT * CTRL + t];
#pragma unroll
        for (int p = 0; p < 4; p++) {
            int idx = tm + p * 256;
            *(float4*)&su[idx * 4] = *(const float4*)&u[((size_t)b * Tt + idx) * CTRL];
        }
        BAR_MND();

        if (tm < 128) {
            // ---- group A (warps 8-11): N recurrence + K ----
            int i = tm;
            if (tm < STATE * CTRL) {
                int o = tm >> 2, c = tm & 3;
                float acc = 0.f;
                for (int ii = 0; ii < LAT; ii++) acc += sWd[ii * STATE + o] * sNall[ii * CTRL + c];
                g_K[(b * Dd) * STATE * CTRL + tm] = acc;
            }
            for (int k = 1; k < Dd; k++) {
                const float* Np = &sNall[(k - 1) * 512];
                float4 a = *(float4*)&Np[i * 4];
                const float* erow = &sE[i * PLD];
#pragma unroll 8
                for (int l = 0; l < LAT; l++) {
                    float e = erow[l];
                    float4 n = *(float4*)&Np[l * 4];
                    a.x += e * n.x; a.y += e * n.y; a.z += e * n.z; a.w += e * n.w;
                }
                *(float4*)&sNall[k * 512 + i * 4] = a;
                BAR_NG();
                if (tm < STATE * CTRL) {
                    int o = tm >> 2, c = tm & 3;
                    float acc = 0.f;
                    for (int ii = 0; ii < LAT; ii++)
                        acc += sWd[ii * STATE + o] * sNall[k * 512 + ii * CTRL + c];
                    g_K[(b * Dd + k) * STATE * CTRL + tm] = acc;
                }
            }
        } else {
            // ---- group B (warps 12-15): M recurrence on tensor ----
            int tg = tm - 128;
            int wq = tg >> 5;

            for (int t = tg; t < LAT * STATE; t += 128)
                g_M[(size_t)(b * Dd) * LAT * STATE + t] = sWd[t];

            for (int r = 1; r < Dd; r++) {
                FragC fm[2];
                wmma::fill_fragment(fm[0], 0.f);
                wmma::fill_fragment(fm[1], 0.f);
#pragma unroll 4
                for (int kk = 0; kk < 16; kk++) {
                    FragBr fb;
                    wmma::load_matrix_sync(fb, &sMp[(kk * 8) * 16], 16);
                    cvt_tf32(fb);
#pragma unroll
                    for (int mt = 0; mt < 2; mt++) {
                        FragAc fa;
                        wmma::load_matrix_sync(fa, &sE[(kk * 8) * PLD + wq * 32 + mt * 16], PLD);
                        cvt_tf32(fa);
                        wmma::mma_sync(fm[mt], fa, fb, fm[mt]);
                    }
                }
                float4 st0, st1, st2, st3;
                st0 = *(float4*)&sMp[tg * 16];
                st1 = *(float4*)&sMp[tg * 16 + 4];
                st2 = *(float4*)&sMp[tg * 16 + 8];
                st3 = *(float4*)&sMp[tg * 16 + 12];
                BAR_MG();
                wmma::store_matrix_sync(&sMp[(wq * 32) * 16], fm[0], 16, wmma::mem_row_major);
                wmma::store_matrix_sync(&sMp[(wq * 32 + 16) * 16], fm[1], 16, wmma::mem_row_major);
                BAR_MG();
                {
                    float4 y0 = *(float4*)&sMp[tg * 16];
                    float4 y1 = *(float4*)&sMp[tg * 16 + 4];
                    float4 y2 = *(float4*)&sMp[tg * 16 + 8];
                    float4 y3 = *(float4*)&sMp[tg * 16 + 12];
                    y0.x += st0.x; y0.y += st0.y; y0.z += st0.z; y0.w += st0.w;
                    y1.x += st1.x; y1.y += st1.y; y1.z += st1.z; y1.w += st1.w;
                    y2.x += st2.x; y2.y += st2.y; y2.z += st2.z; y2.w += st2.w;
                    y3.x += st3.x; y3.y += st3.y; y3.z += st3.z; y3.w += st3.w;
                    *(float4*)&sMp[tg * 16]      = y0;
                    *(float4*)&sMp[tg * 16 + 4]  = y1;
                    *(float4*)&sMp[tg * 16 + 8]  = y2;
                    *(float4*)&sMp[tg * 16 + 12] = y3;
                }
                BAR_MG();
                for (int t = tg; t < LAT * STATE; t += 128)
                    g_M[(size_t)(b * Dd + r) * LAT * STATE + t] =
                        sMp[(t / STATE) * 16 + (t % STATE)];
            }
        }
        BAR_MND();

        // d_j = sum_r N_{7-r} u_{8j+r}
        {
            int i = tm & 127, jh = tm >> 7;
            for (int jj = 0; jj < 64; jj++) {
                int j = jj * 2 + jh;
                float acc = 0.f;
#pragma unroll
                for (int r = 0; r < Dd; r++) {
                    float4 n = *(float4*)&sNall[(7 - r) * 512 + i * 4];
                    float4 uu = *(float4*)&su[(8 * j + r) * 4];
                    acc += dot4(n, uu);
                }
                g_d[((size_t)b * Jn + j) * LAT + i] = acc;
            }
        }
    }
}

// ---------------- decimated scan: 128 steps with A^8, 4-deep d prefetch ----------------
__global__ void __launch_bounds__(128, 4)
k_scan(const float* __restrict__ x_init, const float* __restrict__ Wenc,
       const float* __restrict__ benc) {
    int b = blockIdx.x;
    int i = threadIdx.x;

    __shared__ float zs[2][LAT];
    __shared__ float xi[16];

    ulonglong2 a[32];
    const ulonglong2* Ab = (const ulonglong2*)(g_A8 + (size_t)b * (LAT * LAT) + (size_t)i * LAT);
#pragma unroll
    for (int t = 0; t < 32; t++) a[t] = Ab[t];

    if (i < STATE) xi[i] = x_init[b * STATE + i];
    __syncthreads();

    float z0 = benc[i];
#pragma unroll
    for (int s = 0; s < STATE; s++) z0 += xi[s] * Wenc[s * LAT + i];
    zs[0][i] = z0;
    g_z8[(size_t)b * (Jn + 1) * LAT + i] = z0;
    __syncthreads();

    const float* db = g_d + (size_t)b * Jn * LAT;
    float dreg[4];
#pragma unroll
    for (int p = 0; p < 4; p++) dreg[p] = db[p * LAT + i];
    int cur = 0;

#pragma unroll 4
    for (int k = 0; k < Jn; k++) {
        float ci = dreg[k & 3];
        if (k + 4 < Jn) dreg[k & 3] = db[(k + 4) * LAT + i];

        const ulonglong2* zv2 = (const ulonglong2*)zs[cur];
        unsigned long long acc0 = pack2(ci, 0.f);
        unsigned long long acc1 = 0ULL, acc2 = 0ULL, acc3 = 0ULL;
#pragma unroll
        for (int t = 0; t < 32; t += 2) {
            ulonglong2 zva = zv2[t];
            ulonglong2 zvb = zv2[t + 1];
            ffma2(acc0, a[t].x, zva.x);
            ffma2(acc1, a[t].y, zva.y);
            ffma2(acc2, a[t + 1].x, zvb.x);
            ffma2(acc3, a[t + 1].y, zvb.y);
        }
        float s0, s1, s2, s3, s4, s5, s6, s7;
        unpack2(acc0, s0, s1); unpack2(acc1, s2, s3);
        unpack2(acc2, s4, s5); unpack2(acc3, s6, s7);
        float zn = ((s0 + s2) + (s1 + s3)) + ((s4 + s6) + (s5 + s7));

        zs[cur ^ 1][i] = zn;
        g_z8[((size_t)b * (Jn + 1) + k + 1) * LAT + i] = zn;
        __syncthreads();
        cur ^= 1;
    }
}

// ---------------- X GEMM on tensor cores: X = Z8 @ Mcat ----------------
// A = z8 rows [129 x 128] (row 128 handled scalar), B = Mcat [128 x 128] (r*16+o cols).
__global__ void __launch_bounds__(256)
k_xg() {
    __shared__ float sZA[129 * 36];   // [j][kk], tf32-rounded
    __shared__ float sM2[32 * 132];   // [kk][col], tf32-rounded
    int b = blockIdx.x, tid = threadIdx.x, w = tid >> 5;
    int wm = w & 3, wn = w >> 2;

    FragC fc[2][4];
#pragma unroll
    for (int mt = 0; mt < 2; mt++)
#pragma unroll
        for (int nt = 0; nt < 4; nt++) wmma::fill_fragment(fc[mt][nt], 0.f);
    float acc128 = 0.f;
    int r13 = 0, o13 = 0;
    if (tid < 104) { r13 = tid / 13; o13 = tid % 13; }

    for (int k0 = 0; k0 < 128; k0 += 32) {
        __syncthreads();
        for (int t = tid; t < 129 * 8; t += 256) {
            int j = t >> 3, kq = (t & 7) * 4;
            float4 v = *(const float4*)&g_z8[((size_t)b * (Jn + 1) + j) * LAT + k0 + kq];
            v.x = wmma::__float_to_tf32(v.x);
            v.y = wmma::__float_to_tf32(v.y);
            v.z = wmma::__float_to_tf32(v.z);
            v.w = wmma::__float_to_tf32(v.w);
            *(float4*)&sZA[j * 36 + kq] = v;
        }
        for (int t = tid; t < 32 * 128; t += 256) {
            int kk = t >> 7, col = t & 127;
            int r = col >> 4, o = col & 15;
            float vv = (o < STATE)
                ? g_M[((size_t)(b * Dd + r) * LAT + k0 + kk) * STATE + o] : 0.f;
            sM2[kk * 132 + col] = wmma::__float_to_tf32(vv);
        }
        __syncthreads();
#pragma unroll
        for (int kk8 = 0; kk8 < 4; kk8++) {
            FragA fa[2];
#pragma unroll
            for (int mt = 0; mt < 2; mt++)
                wmma::load_matrix_sync(fa[mt], &sZA[(wm * 32 + mt * 16) * 36 + kk8 * 8], 36);
#pragma unroll
            for (int nt = 0; nt < 4; nt++) {
                FragBr fb;
                wmma::load_matrix_sync(fb, &sM2[(kk8 * 8) * 132 + wn * 64 + nt * 16], 132);
                wmma::mma_sync(fc[0][nt], fa[0], fb, fc[0][nt]);
                wmma::mma_sync(fc[1][nt], fa[1], fb, fc[1][nt]);
            }
        }
        if (tid < 104) {
            float accl = 0.f;
#pragma unroll 8
            for (int kk = 0; kk < 32; kk++)
                accl += sZA[128 * 36 + kk] * sM2[kk * 132 + r13 * 16 + o13];
            acc128 += accl;
        }
    }
    float* X = (float*)g_X4 + (size_t)b * (Jn + 1) * 128;
#pragma unroll
    for (int mt = 0; mt < 2; mt++)
#pragma unroll
        for (int nt = 0; nt < 4; nt++)
            wmma::store_matrix_sync(
                &X[(size_t)(wm * 32 + mt * 16) * 128 + wn * 64 + nt * 16],
                fc[mt][nt], 128, wmma::mem_row_major);
    if (tid < 104)
        X[(size_t)128 * 128 + r13 * 16 + o13] = acc128;
}

// ---------------- final: u-corrections + bias + normalize + write out ----------------
__global__ void __launch_bounds__(256)
k_norm(const float* __restrict__ u, const float* __restrict__ bdec,
       float* __restrict__ outp) {
    int b = blockIdx.y, t0 = blockIdx.x * 256, tid = threadIdx.x;
    __shared__ float sK[Dd * STATE * CTRL];
    __shared__ float4 su[256];
    __shared__ float sb[STATE];
    __shared__ float sO[256 * STATE];

    for (int q = tid; q < Dd * STATE * CTRL; q += 256) sK[q] = g_K[b * Dd * STATE * CTRL + q];
    if (t0 + tid < Tt) su[tid] = *(const float4*)&u[((size_t)b * Tt + t0 + tid) * CTRL];
    if (tid < STATE) sb[tid] = bdec[tid];
    __syncthreads();

    int t = t0 + tid;
    if (t <= Tt) {
        int j = t >> 3, r = t & 7;
        const float* xr = (const float*)g_X4 + ((size_t)b * (Jn + 1) + j) * 128 + r * 16;
        float4 x0 = *(const float4*)&xr[0];
        float4 x1 = *(const float4*)&xr[4];
        float4 x2 = *(const float4*)&xr[8];
        float4 x3 = *(const float4*)&xr[12];
        float x[13] = {x0.x, x0.y, x0.z, x0.w, x1.x, x1.y, x1.z, x1.w,
                       x2.x, x2.y, x2.z, x2.w, x3.x};
#pragma unroll
        for (int o = 0; o < STATE; o++) x[o] += sb[o];
        for (int s = 0; s < r; s++) {
            float4 uu = su[tid - r + s];
            const float* Kp = &sK[(r - 1 - s) * STATE * CTRL];
#pragma unroll
            for (int o = 0; o < STATE; o++)
                x[o] += Kp[o * 4 + 0] * uu.x + Kp[o * 4 + 1] * uu.y +
                        Kp[o * 4 + 2] * uu.z + Kp[o * 4 + 3] * uu.w;
        }
        float nrm = sqrtf(x[3] * x[3] + x[4] * x[4] + x[5] * x[5] + x[6] * x[6]);
        float inv = 1.0f / fmaxf(nrm, 1e-12f);
        x[3] *= inv; x[4] *= inv; x[5] *= inv; x[6] *= inv;
#pragma unroll
        for (int o = 0; o < STATE; o++) sO[tid * STATE + o] = x[o];
    }
    __syncthreads();
    int nrow = Tt + 1 - t0;
    if (nrow > 256) nrow = 256;
    if (nrow < 0) nrow = 0;
    for (int q = tid; q < nrow * STATE; q += 256)
        outp[((size_t)b * (Tt + 1) + t0) * STATE + q] = sO[q];
}

// ---------------- launcher ----------------
extern "C" void kernel_launch(void* const* d_in, const int* in_sizes, int n_in,
                              void* d_out, int out_size) {
    const float* x_history = (const float*)d_in[0];
    const float* u_history = (const float*)d_in[1];
    const float* x_init    = (const float*)d_in[2];
    const float* u_future  = (const float*)d_in[4];
    const float* W_ctxt    = (const float*)d_in[6];
    const float* b_ctxt    = (const float*)d_in[7];
    const float* W_A       = (const float*)d_in[8];
    const float* b_A       = (const float*)d_in[9];
    const float* W_B       = (const float*)d_in[10];
    const float* b_B       = (const float*)d_in[11];
    const float* W_enc     = (const float*)d_in[12];
    const float* b_enc     = (const float*)d_in[13];
    const float* W_dec     = (const float*)d_in[14];
    const float* b_dec     = (const float*)d_in[15];
    float* out = (float*)d_out;

    const int GE_SMEM = (2 * 128 * 36 + 2 * 32 * 132) * 4;        // 70656 B
    const int PM_SMEM =
        (128 * PLD + 128 * PLD + 128 * 16 + 128 * STATE + 8 * 128 * 4 + 1024 * 4) * 4;
    cudaFuncSetAttribute(k_gemmE_tc, cudaFuncAttributeMaxDynamicSharedMemorySize, GE_SMEM);
    cudaFuncSetAttribute(k_powmnd, cudaFuncAttributeMaxDynamicSharedMemorySize, PM_SMEM);

    k_ctxt<<<Bn, 256>>>(x_history, u_history, W_ctxt, b_ctxt);
    k_gemmE_tc<<<dim3(128, 4), 256, GE_SMEM>>>(W_A);
    k_gemmB<<<Bn, 256>>>(W_B, b_B);

    k_powmnd<<<Bn, 512, PM_SMEM>>>(b_A, W_dec, u_future);

    k_scan<<<Bn, 128>>>(x_init, W_enc, b_enc);

    k_xg<<<Bn, 256>>>();
    k_norm<<<dim3(5, Bn), 256>>>(u_future, b_dec, out);
}

// round 15
// speedup vs baseline: 1.3174x; 1.1536x over previous
#include <cuda_runtime.h>
#include <mma.h>
#include <cstdint>

using namespace nvcuda;

// Problem constants
#define Bn    512
#define Hh    50
#define Tt    1024
#define STATE 13
#define CTRL  4
#define LAT   128
#define HID   256
#define Dd    8            // decimation factor
#define Jn    (Tt / Dd)    // 128 sequential steps

// ---------------- scratch (no allocations allowed) ----------------
__device__ float  g_h[Bn * HID];
__device__ float  g_E [(size_t)Bn * LAT * LAT];    // raw h@W_A product (bias NOT added)
__device__ float  g_A8[(size_t)Bn * LAT * LAT];    // A^8 (incl. identity)
__device__ float  g_Bm[Bn * LAT * CTRL];
__device__ float  g_M [(size_t)Bn * Dd * LAT * STATE]; // M_r = (A^T)^r Wdec
__device__ float  g_K [Bn * Dd * STATE * CTRL];    // K_k = Wdec^T A^k B
__device__ float  g_d [(size_t)Bn * Jn * LAT];     // d_j
__device__ float  g_z8[(size_t)Bn * (Jn + 1) * LAT];
__device__ float4 g_X4[(size_t)Bn * (Jn + 1) * 32];  // X rows 128-wide: [b][j][r*16+o]

// ---------------- helpers ----------------
__device__ __forceinline__ unsigned long long pack2(float x, float y) {
    unsigned long long r;
    asm("mov.b64 %0, {%1, %2};" : "=l"(r) : "f"(x), "f"(y));
    return r;
}
__device__ __forceinline__ void unpack2(unsigned long long v, float& x, float& y) {
    asm("mov.b64 {%0, %1}, %2;" : "=f"(x), "=f"(y) : "l"(v));
}
__device__ __forceinline__ void ffma2(unsigned long long& d, unsigned long long a,
                                      unsigned long long b) {
    asm("fma.rn.f32x2 %0, %1, %2, %3;" : "=l"(d) : "l"(a), "l"(b), "l"(d));
}
__device__ __forceinline__ float dot4(float4 a, float4 b) {
    return a.x * b.x + a.y * b.y + a.z * b.z + a.w * b.w;
}
__device__ __forceinline__ void cp_async16(void* smem_dst, const void* gmem_src) {
    uint32_t s = (uint32_t)__cvta_generic_to_shared(smem_dst);
    asm volatile("cp.async.cg.shared.global [%0], [%1], 16;" :: "r"(s), "l"(gmem_src));
}
#define CP_COMMIT()  asm volatile("cp.async.commit_group;" ::: "memory")
#define CP_WAIT1()   asm volatile("cp.async.wait_group 1;" ::: "memory")
#define CP_WAIT0()   asm volatile("cp.async.wait_group 0;" ::: "memory")
#define BAR_POW()   asm volatile("bar.sync 1, 256;" ::: "memory")
#define BAR_MND()   asm volatile("bar.sync 2, 256;" ::: "memory")
#define BAR_NG()    asm volatile("bar.sync 3, 128;" ::: "memory")
#define BAR_MG()    asm volatile("bar.sync 4, 128;" ::: "memory")

// ---------------- wmma types ----------------
typedef wmma::fragment<wmma::matrix_a, 16, 16, 8, wmma::precision::tf32, wmma::row_major> FragA;
typedef wmma::fragment<wmma::matrix_a, 16, 16, 8, wmma::precision::tf32, wmma::col_major> FragAc;
typedef wmma::fragment<wmma::matrix_b, 16, 16, 8, wmma::precision::tf32, wmma::row_major> FragBr;
typedef wmma::fragment<wmma::accumulator, 16, 16, 8, float> FragC;

template <typename F>
__device__ __forceinline__ void cvt_tf32(F& f) {
#pragma unroll
    for (int e = 0; e < f.num_elements; e++) f.x[e] = wmma::__float_to_tf32(f.x[e]);
}

// ---------------- kernel 1: context mean + tanh MLP ----------------
__global__ void k_ctxt(const float* __restrict__ xh, const float* __restrict__ uh,
                       const float* __restrict__ Wc, const float* __restrict__ bc) {
    int b = blockIdx.x;
    int tid = threadIdx.x;
    __shared__ float m[STATE + CTRL];

    if (tid < STATE + CTRL) {
        float s = 0.f;
        if (tid < STATE) {
            const float* p = xh + (size_t)b * Hh * STATE + tid;
            for (int r = 0; r < Hh; r++) s += p[r * STATE];
        } else {
            const float* p = uh + (size_t)b * Hh * CTRL + (tid - STATE);
            for (int r = 0; r < Hh; r++) s += p[r * CTRL];
        }
        m[tid] = s * (1.0f / (float)Hh);
    }
    __syncthreads();

    float acc = bc[tid];
#pragma unroll
    for (int c = 0; c < STATE + CTRL; c++) acc += m[c] * Wc[c * HID + tid];
    g_h[b * HID + tid] = tanhf(acc);
}

// ---------------- kernel 2: E = h @ W_A (tf32, cp.async double-buffered) ----------------
__global__ void __launch_bounds__(256)
k_gemmE_tc(const float* __restrict__ WA) {
    extern __shared__ float esm[];
    float* sA = esm;                  // [2][128*36]
    float* sB = esm + 2 * 128 * 36;   // [2][32*132]
    int tid = threadIdx.x, w = tid >> 5;
    int wm = w & 3, wn = w >> 2;
    int n0g = blockIdx.x * 128;
    int m0g = blockIdx.y * 128;

    FragC fc[2][4];
#pragma unroll
    for (int mt = 0; mt < 2; mt++)
#pragma unroll
        for (int nt = 0; nt < 4; nt++) wmma::fill_fragment(fc[mt][nt], 0.f);

    auto stage = [&](int buf, int k0) {
        float* dA = sA + buf * (128 * 36);
        float* dB = sB + buf * (32 * 132);
#pragma unroll
        for (int p = 0; p < 4; p++) {
            int idx = tid + p * 256;
            int row = idx >> 3, kq = (idx & 7) * 4;
            cp_async16(&dA[row * 36 + kq], &g_h[(m0g + row) * HID + k0 + kq]);
        }
#pragma unroll
        for (int p = 0; p < 4; p++) {
            int idx = tid + p * 256;
            int kkb = idx >> 5, c4 = (idx & 31) * 4;
            cp_async16(&dB[kkb * 132 + c4],
                       &WA[(size_t)(k0 + kkb) * (LAT * LAT) + n0g + c4]);
        }
        CP_COMMIT();
    };

    stage(0, 0);
    for (int c = 0; c < 8; c++) {
        if (c + 1 < 8) {
            stage((c + 1) & 1, (c + 1) * 32);
            CP_WAIT1();
        } else {
            CP_WAIT0();
        }
        __syncthreads();
        const float* cA = sA + (c & 1) * (128 * 36);
        const float* cB = sB + (c & 1) * (32 * 132);
#pragma unroll
        for (int kk8 = 0; kk8 < 4; kk8++) {
            FragA fa[2];
#pragma unroll
            for (int mt = 0; mt < 2; mt++) {
                wmma::load_matrix_sync(fa[mt], &cA[(wm * 32 + mt * 16) * 36 + kk8 * 8], 36);
                cvt_tf32(fa[mt]);
            }
#pragma unroll
            for (int nt = 0; nt < 4; nt++) {
                FragBr fb;
                wmma::load_matrix_sync(fb, &cB[(kk8 * 8) * 132 + wn * 64 + nt * 16], 132);
                cvt_tf32(fb);
                wmma::mma_sync(fc[0][nt], fa[0], fb, fc[0][nt]);
                wmma::mma_sync(fc[1][nt], fa[1], fb, fc[1][nt]);
            }
        }
        __syncthreads();
    }
#pragma unroll
    for (int mt = 0; mt < 2; mt++)
#pragma unroll
        for (int nt = 0; nt < 4; nt++)
            wmma::store_matrix_sync(
                &g_E[(size_t)(m0g + wm * 32 + mt * 16) * (LAT * LAT) +
                     n0g + wn * 64 + nt * 16],
                fc[mt][nt], LAT * LAT, wmma::mem_row_major);
}

// ---------------- kernel 3: B_mat = h @ W_B + b_B ----------------
__global__ void k_gemmB(const float* __restrict__ WB, const float* __restrict__ bB) {
    int b = blockIdx.x;
    int tid = threadIdx.x;
    __shared__ float hs[HID];
    hs[tid] = g_h[b * HID + tid];
    __syncthreads();
    for (int c = tid; c < LAT * CTRL; c += 256) {
        float acc = bB[c];
#pragma unroll 8
        for (int k = 0; k < HID; k++) acc += hs[k] * WB[k * (LAT * CTRL) + c];
        g_Bm[b * (LAT * CTRL) + c] = acc;
    }
}

// ================= fused k_powmnd: warp-specialized, 3-way =================
#define PLD 132
__global__ void __launch_bounds__(512)
k_powmnd(const float* __restrict__ bA, const float* __restrict__ Wdec,
         const float* __restrict__ u) {
    extern __shared__ float dsm[];
    float* sX    = dsm;                      // 128*132 (tf32-rounded, pow's buffer)
    float* sE    = sX + 128 * PLD;           // 128*132 (fp32, mnd's buffer)
    float* sMp   = sE + 128 * PLD;           // 128*16
    float* sWd   = sMp + 128 * 16;           // 128*13
    float* sNall = sWd + 128 * STATE;        // 8*128*4
    float* su    = sNall + 8 * 128 * 4;      // 1024*4
    int b = blockIdx.x, tid = threadIdx.x;
    const float* Eb = g_E + (size_t)b * (LAT * LAT);

#pragma unroll
    for (int p = 0; p < 8; p++) {
        int idx = tid + p * 512;
        int row = idx >> 5, c4 = (idx & 31) * 4;
        float4 e = *(const float4*)&Eb[row * 128 + c4];
        float4 bb = *(const float4*)&bA[row * 128 + c4];
        e.x += bb.x; e.y += bb.y; e.z += bb.z; e.w += bb.w;
        *(float4*)&sE[row * PLD + c4] = e;
        e.x = wmma::__float_to_tf32(e.x);
        e.y = wmma::__float_to_tf32(e.y);
        e.z = wmma::__float_to_tf32(e.z);
        e.w = wmma::__float_to_tf32(e.w);
        *(float4*)&sX[row * PLD + c4] = e;
    }
    __syncthreads();

    if (tid < 256) {
        // ================= POW half (warps 0-7) =================
        int w = tid >> 5, wm = w & 3, wn = w >> 2;
        float* A8b = g_A8 + (size_t)b * (LAT * LAT);

        for (int rnd = 0; rnd < 3; rnd++) {
            FragC fc[2][4];
#pragma unroll
            for (int mt = 0; mt < 2; mt++)
#pragma unroll
                for (int nt = 0; nt < 4; nt++) wmma::fill_fragment(fc[mt][nt], 0.f);

#pragma unroll 4
            for (int kk = 0; kk < 16; kk++) {
                FragA fa[2];
#pragma unroll
                for (int mt = 0; mt < 2; mt++)
                    wmma::load_matrix_sync(fa[mt], &sX[(wm * 32 + mt * 16) * PLD + kk * 8], PLD);
#pragma unroll
                for (int nt = 0; nt < 4; nt++) {
                    FragBr fb;
                    wmma::load_matrix_sync(fb, &sX[(kk * 8) * PLD + wn * 64 + nt * 16], PLD);
                    wmma::mma_sync(fc[0][nt], fa[0], fb, fc[0][nt]);
                    wmma::mma_sync(fc[1][nt], fa[1], fb, fc[1][nt]);
                }
            }
            BAR_POW();

            int r0l = tid >> 3;
            int cb = (tid & 7) * 16;
#pragma unroll
            for (int ph = 0; ph < 4; ph++) {
                int row = ph * 32 + r0l;
                float4 st[4];
#pragma unroll
                for (int q = 0; q < 4; q++) st[q] = *(float4*)&sX[row * PLD + cb + q * 4];
                BAR_POW();
                if (wm == ph) {
#pragma unroll
                    for (int mt = 0; mt < 2; mt++)
#pragma unroll
                        for (int nt = 0; nt < 4; nt++)
                            wmma::store_matrix_sync(
                                &sX[(ph * 32 + mt * 16) * PLD + wn * 64 + nt * 16],
                                fc[mt][nt], PLD, wmma::mem_row_major);
                }
                BAR_POW();
                if (rnd < 2) {
#pragma unroll
                    for (int q = 0; q < 4; q++) {
                        float4 y = *(float4*)&sX[row * PLD + cb + q * 4];
                        y.x = wmma::__float_to_tf32(y.x + 2.f * st[q].x);
                        y.y = wmma::__float_to_tf32(y.y + 2.f * st[q].y);
                        y.z = wmma::__float_to_tf32(y.z + 2.f * st[q].z);
                        y.w = wmma::__float_to_tf32(y.w + 2.f * st[q].w);
                        *(float4*)&sX[row * PLD + cb + q * 4] = y;
                    }
                } else {
#pragma unroll
                    for (int q = 0; q < 4; q++) {
                        float4 y = *(float4*)&sX[row * PLD + cb + q * 4];
                        int c0 = cb + q * 4;
                        y.x += 2.f * st[q].x + ((row == c0 + 0) ? 1.f : 0.f);
                        y.y += 2.f * st[q].y + ((row == c0 + 1) ? 1.f : 0.f);
                        y.z += 2.f * st[q].z + ((row == c0 + 2) ? 1.f : 0.f);
                        y.w += 2.f * st[q].w + ((row == c0 + 3) ? 1.f : 0.f);
                        *(float4*)&A8b[row * 128 + c0] = y;
                    }
                }
                BAR_POW();
            }
        }
    } else {
        // ================= MND half (warps 8-15) =================
        int tm = tid - 256;

        for (int t = tm; t < 128 * 16; t += 256) {
            int row = t >> 4, o = t & 15;
            sMp[t] = (o < STATE) ? Wdec[row * STATE + o] : 0.f;
        }
        for (int t = tm; t < LAT * STATE; t += 256) sWd[t] = Wdec[t];
        for (int t = tm; t < LAT * CTRL; t += 256) sNall[t] = g_Bm[b * LAT * CTRL + t];
#pragma unroll
        for (int p = 0; p < 4; p++) {
            int idx = tm + p * 256;
            *(float4*)&su[idx * 4] = *(const float4*)&u[((size_t)b * Tt + idx) * CTRL];
        }
        BAR_MND();

        if (tm < 128) {
            // ---- group A (warps 8-11): N recurrence + K ----
            int i = tm;
            if (tm < STATE * CTRL) {
                int o = tm >> 2, c = tm & 3;
                float acc = 0.f;
                for (int ii = 0; ii < LAT; ii++) acc += sWd[ii * STATE + o] * sNall[ii * CTRL + c];
                g_K[(b * Dd) * STATE * CTRL + tm] = acc;
            }
            for (int k = 1; k < Dd; k++) {
                const float* Np = &sNall[(k - 1) * 512];
                float4 a = *(float4*)&Np[i * 4];
                const float* erow = &sE[i * PLD];
#pragma unroll 8
                for (int l = 0; l < LAT; l++) {
                    float e = erow[l];
                    float4 n = *(float4*)&Np[l * 4];
                    a.x += e * n.x; a.y += e * n.y; a.z += e * n.z; a.w += e * n.w;
                }
                *(float4*)&sNall[k * 512 + i * 4] = a;
                BAR_NG();
                if (tm < STATE * CTRL) {
                    int o = tm >> 2, c = tm & 3;
                    float acc = 0.f;
                    for (int ii = 0; ii < LAT; ii++)
                        acc += sWd[ii * STATE + o] * sNall[k * 512 + ii * CTRL + c];
                    g_K[(b * Dd + k) * STATE * CTRL + tm] = acc;
                }
            }
        } else {
            // ---- group B (warps 12-15): M recurrence on tensor ----
            int tg = tm - 128;
            int wq = tg >> 5;

            for (int t = tg; t < LAT * STATE; t += 128)
                g_M[(size_t)(b * Dd) * LAT * STATE + t] = sWd[t];

            for (int r = 1; r < Dd; r++) {
                FragC fm[2];
                wmma::fill_fragment(fm[0], 0.f);
                wmma::fill_fragment(fm[1], 0.f);
#pragma unroll 4
                for (int kk = 0; kk < 16; kk++) {
                    FragBr fb;
                    wmma::load_matrix_sync(fb, &sMp[(kk * 8) * 16], 16);
                    cvt_tf32(fb);
#pragma unroll
                    for (int mt = 0; mt < 2; mt++) {
                        FragAc fa;
                        wmma::load_matrix_sync(fa, &sE[(kk * 8) * PLD + wq * 32 + mt * 16], PLD);
                        cvt_tf32(fa);
                        wmma::mma_sync(fm[mt], fa, fb, fm[mt]);
                    }
                }
                float4 st0, st1, st2, st3;
                st0 = *(float4*)&sMp[tg * 16];
                st1 = *(float4*)&sMp[tg * 16 + 4];
                st2 = *(float4*)&sMp[tg * 16 + 8];
                st3 = *(float4*)&sMp[tg * 16 + 12];
                BAR_MG();
                wmma::store_matrix_sync(&sMp[(wq * 32) * 16], fm[0], 16, wmma::mem_row_major);
                wmma::store_matrix_sync(&sMp[(wq * 32 + 16) * 16], fm[1], 16, wmma::mem_row_major);
                BAR_MG();
                {
                    float4 y0 = *(float4*)&sMp[tg * 16];
                    float4 y1 = *(float4*)&sMp[tg * 16 + 4];
                    float4 y2 = *(float4*)&sMp[tg * 16 + 8];
                    float4 y3 = *(float4*)&sMp[tg * 16 + 12];
                    y0.x += st0.x; y0.y += st0.y; y0.z += st0.z; y0.w += st0.w;
                    y1.x += st1.x; y1.y += st1.y; y1.z += st1.z; y1.w += st1.w;
                    y2.x += st2.x; y2.y += st2.y; y2.z += st2.z; y2.w += st2.w;
                    y3.x += st3.x; y3.y += st3.y; y3.z += st3.z; y3.w += st3.w;
                    *(float4*)&sMp[tg * 16]      = y0;
                    *(float4*)&sMp[tg * 16 + 4]  = y1;
                    *(float4*)&sMp[tg * 16 + 8]  = y2;
                    *(float4*)&sMp[tg * 16 + 12] = y3;
                }
                BAR_MG();
                for (int t = tg; t < LAT * STATE; t += 128)
                    g_M[(size_t)(b * Dd + r) * LAT * STATE + t] =
                        sMp[(t / STATE) * 16 + (t % STATE)];
            }
        }
        BAR_MND();

        // d_j = sum_r N_{7-r} u_{8j+r}
        {
            int i = tm & 127, jh = tm >> 7;
            for (int jj = 0; jj < 64; jj++) {
                int j = jj * 2 + jh;
                float acc = 0.f;
#pragma unroll
                for (int r = 0; r < Dd; r++) {
                    float4 n = *(float4*)&sNall[(7 - r) * 512 + i * 4];
                    float4 uu = *(float4*)&su[(8 * j + r) * 4];
                    acc += dot4(n, uu);
                }
                g_d[((size_t)b * Jn + j) * LAT + i] = acc;
            }
        }
    }
}

// ---------------- decimated scan: 128 steps with A^8, 4-deep d prefetch ----------------
// occ 3 (NOT 4): A residency needs ~167 regs; forcing 4 CTAs/SM spills the hot loop.
__global__ void __launch_bounds__(128, 3)
k_scan(const float* __restrict__ x_init, const float* __restrict__ Wenc,
       const float* __restrict__ benc) {
    int b = blockIdx.x;
    int i = threadIdx.x;

    __shared__ float zs[2][LAT];
    __shared__ float xi[16];

    ulonglong2 a[32];
    const ulonglong2* Ab = (const ulonglong2*)(g_A8 + (size_t)b * (LAT * LAT) + (size_t)i * LAT);
#pragma unroll
    for (int t = 0; t < 32; t++) a[t] = Ab[t];

    if (i < STATE) xi[i] = x_init[b * STATE + i];
    __syncthreads();

    float z0 = benc[i];
#pragma unroll
    for (int s = 0; s < STATE; s++) z0 += xi[s] * Wenc[s * LAT + i];
    zs[0][i] = z0;
    g_z8[(size_t)b * (Jn + 1) * LAT + i] = z0;
    __syncthreads();

    const float* db = g_d + (size_t)b * Jn * LAT;
    float dreg[4];
#pragma unroll
    for (int p = 0; p < 4; p++) dreg[p] = db[p * LAT + i];
    int cur = 0;

#pragma unroll 4
    for (int k = 0; k < Jn; k++) {
        float ci = dreg[k & 3];
        if (k + 4 < Jn) dreg[k & 3] = db[(k + 4) * LAT + i];

        const ulonglong2* zv2 = (const ulonglong2*)zs[cur];
        unsigned long long acc0 = pack2(ci, 0.f);
        unsigned long long acc1 = 0ULL, acc2 = 0ULL, acc3 = 0ULL;
#pragma unroll
        for (int t = 0; t < 32; t += 2) {
            ulonglong2 zva = zv2[t];
            ulonglong2 zvb = zv2[t + 1];
            ffma2(acc0, a[t].x, zva.x);
            ffma2(acc1, a[t].y, zva.y);
            ffma2(acc2, a[t + 1].x, zvb.x);
            ffma2(acc3, a[t + 1].y, zvb.y);
        }
        float s0, s1, s2, s3, s4, s5, s6, s7;
        unpack2(acc0, s0, s1); unpack2(acc1, s2, s3);
        unpack2(acc2, s4, s5); unpack2(acc3, s6, s7);
        float zn = ((s0 + s2) + (s1 + s3)) + ((s4 + s6) + (s5 + s7));

        zs[cur ^ 1][i] = zn;
        g_z8[((size_t)b * (Jn + 1) + k + 1) * LAT + i] = zn;
        __syncthreads();
        cur ^= 1;
    }
}

// ---------------- X GEMM on tensor cores: X = Z8 @ Mcat ----------------
__global__ void __launch_bounds__(256)
k_xg() {
    __shared__ float sZA[129 * 36];   // [j][kk], tf32-rounded
    __shared__ float sM2[32 * 132];   // [kk][col], tf32-rounded
    int b = blockIdx.x, tid = threadIdx.x, w = tid >> 5;
    int wm = w & 3, wn = w >> 2;

    FragC fc[2][4];
#pragma unroll
    for (int mt = 0; mt < 2; mt++)
#pragma unroll
        for (int nt = 0; nt < 4; nt++) wmma::fill_fragment(fc[mt][nt], 0.f);
    float acc128 = 0.f;
    int r13 = 0, o13 = 0;
    if (tid < 104) { r13 = tid / 13; o13 = tid % 13; }

    for (int k0 = 0; k0 < 128; k0 += 32) {
        __syncthreads();
        for (int t = tid; t < 129 * 8; t += 256) {
            int j = t >> 3, kq = (t & 7) * 4;
            float4 v = *(const float4*)&g_z8[((size_t)b * (Jn + 1) + j) * LAT + k0 + kq];
            v.x = wmma::__float_to_tf32(v.x);
            v.y = wmma::__float_to_tf32(v.y);
            v.z = wmma::__float_to_tf32(v.z);
            v.w = wmma::__float_to_tf32(v.w);
            *(float4*)&sZA[j * 36 + kq] = v;
        }
        for (int t = tid; t < 32 * 128; t += 256) {
            int kk = t >> 7, col = t & 127;
            int r = col >> 4, o = col & 15;
            float vv = (o < STATE)
                ? g_M[((size_t)(b * Dd + r) * LAT + k0 + kk) * STATE + o] : 0.f;
            sM2[kk * 132 + col] = wmma::__float_to_tf32(vv);
        }
        __syncthreads();
#pragma unroll
        for (int kk8 = 0; kk8 < 4; kk8++) {
            FragA fa[2];
#pragma unroll
            for (int mt = 0; mt < 2; mt++)
                wmma::load_matrix_sync(fa[mt], &sZA[(wm * 32 + mt * 16) * 36 + kk8 * 8], 36);
#pragma unroll
            for (int nt = 0; nt < 4; nt++) {
                FragBr fb;
                wmma::load_matrix_sync(fb, &sM2[(kk8 * 8) * 132 + wn * 64 + nt * 16], 132);
                wmma::mma_sync(fc[0][nt], fa[0], fb, fc[0][nt]);
                wmma::mma_sync(fc[1][nt], fa[1], fb, fc[1][nt]);
            }
        }
        if (tid < 104) {
            float accl = 0.f;
#pragma unroll 8
            for (int kk = 0; kk < 32; kk++)
                accl += sZA[128 * 36 + kk] * sM2[kk * 132 + r13 * 16 + o13];
            acc128 += accl;
        }
    }
    float* X = (float*)g_X4 + (size_t)b * (Jn + 1) * 128;
#pragma unroll
    for (int mt = 0; mt < 2; mt++)
#pragma unroll
        for (int nt = 0; nt < 4; nt++)
            wmma::store_matrix_sync(
                &X[(size_t)(wm * 32 + mt * 16) * 128 + wn * 64 + nt * 16],
                fc[mt][nt], 128, wmma::mem_row_major);
    if (tid < 104)
        X[(size_t)128 * 128 + r13 * 16 + o13] = acc128;
}

// ---------------- final: u-corrections + bias + normalize + write out ----------------
__global__ void __launch_bounds__(256)
k_norm(const float* __restrict__ u, const float* __restrict__ bdec,
       float* __restrict__ outp) {
    int b = blockIdx.y, t0 = blockIdx.x * 256, tid = threadIdx.x;
    __shared__ float sK[Dd * STATE * CTRL];
    __shared__ float4 su[256];
    __shared__ float sb[STATE];
    __shared__ float sO[256 * STATE];

    for (int q = tid; q < Dd * STATE * CTRL; q += 256) sK[q] = g_K[b * Dd * STATE * CTRL + q];
    if (t0 + tid < Tt) su[tid] = *(const float4*)&u[((size_t)b * Tt + t0 + tid) * CTRL];
    if (tid < STATE) sb[tid] = bdec[tid];
    __syncthreads();

    int t = t0 + tid;
    if (t <= Tt) {
        int j = t >> 3, r = t & 7;
        const float* xr = (const float*)g_X4 + ((size_t)b * (Jn + 1) + j) * 128 + r * 16;
        float4 x0 = *(const float4*)&xr[0];
        float4 x1 = *(const float4*)&xr[4];
        float4 x2 = *(const float4*)&xr[8];
        float4 x3 = *(const float4*)&xr[12];
        float x[13] = {x0.x, x0.y, x0.z, x0.w, x1.x, x1.y, x1.z, x1.w,
                       x2.x, x2.y, x2.z, x2.w, x3.x};
#pragma unroll
        for (int o = 0; o < STATE; o++) x[o] += sb[o];
        for (int s = 0; s < r; s++) {
            float4 uu = su[tid - r + s];
            const float* Kp = &sK[(r - 1 - s) * STATE * CTRL];
#pragma unroll
            for (int o = 0; o < STATE; o++)
                x[o] += Kp[o * 4 + 0] * uu.x + Kp[o * 4 + 1] * uu.y +
                        Kp[o * 4 + 2] * uu.z + Kp[o * 4 + 3] * uu.w;
        }
        float nrm = sqrtf(x[3] * x[3] + x[4] * x[4] + x[5] * x[5] + x[6] * x[6]);
        float inv = 1.0f / fmaxf(nrm, 1e-12f);
        x[3] *= inv; x[4] *= inv; x[5] *= inv; x[6] *= inv;
#pragma unroll
        for (int o = 0; o < STATE; o++) sO[tid * STATE + o] = x[o];
    }
    __syncthreads();
    int nrow = Tt + 1 - t0;
    if (nrow > 256) nrow = 256;
    if (nrow < 0) nrow = 0;
    for (int q = tid; q < nrow * STATE; q += 256)
        outp[((size_t)b * (Tt + 1) + t0) * STATE + q] = sO[q];
}

// ---------------- launcher ----------------
extern "C" void kernel_launch(void* const* d_in, const int* in_sizes, int n_in,
                              void* d_out, int out_size) {
    const float* x_history = (const float*)d_in[0];
    const float* u_history = (const float*)d_in[1];
    const float* x_init    = (const float*)d_in[2];
    const float* u_future  = (const float*)d_in[4];
    const float* W_ctxt    = (const float*)d_in[6];
    const float* b_ctxt    = (const float*)d_in[7];
    const float* W_A       = (const float*)d_in[8];
    const float* b_A       = (const float*)d_in[9];
    const float* W_B       = (const float*)d_in[10];
    const float* b_B       = (const float*)d_in[11];
    const float* W_enc     = (const float*)d_in[12];
    const float* b_enc     = (const float*)d_in[13];
    const float* W_dec     = (const float*)d_in[14];
    const float* b_dec     = (const float*)d_in[15];
    float* out = (float*)d_out;

    const int GE_SMEM = (2 * 128 * 36 + 2 * 32 * 132) * 4;        // 70656 B
    const int PM_SMEM =
        (128 * PLD + 128 * PLD + 128 * 16 + 128 * STATE + 8 * 128 * 4 + 1024 * 4) * 4;
    cudaFuncSetAttribute(k_gemmE_tc, cudaFuncAttributeMaxDynamicSharedMemorySize, GE_SMEM);
    cudaFuncSetAttribute(k_powmnd, cudaFuncAttributeMaxDynamicSharedMemorySize, PM_SMEM);

    k_ctxt<<<Bn, 256>>>(x_history, u_history, W_ctxt, b_ctxt);
    k_gemmE_tc<<<dim3(128, 4), 256, GE_SMEM>>>(W_A);
    k_gemmB<<<Bn, 256>>>(W_B, b_B);

    k_powmnd<<<Bn, 512, PM_SMEM>>>(b_A, W_dec, u_future);

    k_scan<<<Bn, 128>>>(x_init, W_enc, b_enc);

    k_xg<<<Bn, 256>>>();
    k_norm<<<dim3(5, Bn), 256>>>(u_future, b_dec, out);
}